// round 2
// baseline (speedup 1.0000x reference)
#include <cuda_runtime.h>
#include <cstddef>

#define TT 100
#define BB 16384
#define IN 6
#define EH 8
#define SH 24
#define CH 16
#define NC 3
#define RH 16

// All weights + biases: 1384 floats -> constant memory (LDCU uniform port,
// off the fma pipe and LSU).
struct Weights {
    float We_c[EH * IN]; float be_c[EH];
    float We_r[EH * IN]; float be_r[EH];
    float Ws[SH * 2 * EH]; float bs[SH];
    float Wch[CH * SH];  float bch[CH];
    float Wco[NC * CH];  float bco[NC];
    float Wrh[RH * SH];  float brh[RH];
    float Wro[RH];       float bro[1];
};

__constant__ Weights cw;

// snntorch Leaky, reset='subtract', THR=1, BETA=0.9.
// (m - 1 > 0) == (m > 1) exactly in fp32 (Sterbenz / sign preservation).
__device__ __forceinline__ void lif_update(float cur, float& m, float& s) {
    float mold = m;
    m = fmaf(0.9f, m, cur);
    if (mold > 1.0f) m -= 1.0f;
    s = (m > 1.0f) ? 1.0f : 0.0f;
}

__global__ void __launch_bounds__(128, 1)
snn_kernel(const float* __restrict__ x, float* __restrict__ out)
{
    const int b = blockIdx.x * 128 + threadIdx.x;

    float m_ec[EH], m_er[EH], m_sh[SH], m_ch[CH], m_co[NC], m_rh[RH], m_ro;
#pragma unroll
    for (int i = 0; i < EH; ++i) { m_ec[i] = 0.f; m_er[i] = 0.f; }
#pragma unroll
    for (int i = 0; i < SH; ++i) m_sh[i] = 0.f;
#pragma unroll
    for (int i = 0; i < CH; ++i) m_ch[i] = 0.f;
#pragma unroll
    for (int i = 0; i < NC; ++i) m_co[i] = 0.f;
#pragma unroll
    for (int i = 0; i < RH; ++i) m_rh[i] = 0.f;
    m_ro = 0.f;

    const size_t TB = (size_t)TT * BB;
    float* const p_mco = out;
    float* const p_sch = out + TB * 3;
    float* const p_mro = out + TB * 19;
    float* const p_srh = out + TB * 20;
    float* const p_ssh = out + TB * 36;
    float* const p_sec = out + TB * 60;
    float* const p_ser = out + TB * 68;

#pragma unroll 1
    for (int t = 0; t < TT; ++t) {
        const size_t r = (size_t)t * BB + b;

        const float2* xp = (const float2*)(x + r * IN);
        const float2 a0 = xp[0], a1 = xp[1], a2 = xp[2];
        const float xv[IN] = {a0.x, a0.y, a1.x, a1.y, a2.x, a2.y};

        // ---- encoders: ascending-k fma, bias last (bit-exact vs reference) ----
        float s_ec[EH], s_er[EH];
#pragma unroll
        for (int o = 0; o < EH; ++o) {
            float acc = 0.f;
#pragma unroll
            for (int i = 0; i < IN; ++i) acc = fmaf(xv[i], cw.We_c[o * IN + i], acc);
            lif_update(acc + cw.be_c[o], m_ec[o], s_ec[o]);
        }
#pragma unroll
        for (int o = 0; o < EH; ++o) {
            float acc = 0.f;
#pragma unroll
            for (int i = 0; i < IN; ++i) acc = fmaf(xv[i], cw.We_r[o * IN + i], acc);
            lif_update(acc + cw.be_r[o], m_er[o], s_er[o]);
        }

        // ---- shared layer (bit-exact: ascending) ----
        float s_sh[SH];
#pragma unroll
        for (int o = 0; o < SH; ++o) {
            float acc = 0.f;
#pragma unroll
            for (int i = 0; i < EH; ++i) acc = fmaf(s_ec[i], cw.Ws[o * 2 * EH + i], acc);
#pragma unroll
            for (int i = 0; i < EH; ++i) acc = fmaf(s_er[i], cw.Ws[o * 2 * EH + EH + i], acc);
            lif_update(acc + cw.bs[o], m_sh[o], s_sh[o]);
        }

        // ---- classification hidden (bit-exact: ascending) ----
        float s_ch[CH];
#pragma unroll
        for (int o = 0; o < CH; ++o) {
            float acc = 0.f;
#pragma unroll
            for (int i = 0; i < SH; ++i) acc = fmaf(s_sh[i], cw.Wch[o * SH + i], acc);
            lif_update(acc + cw.bch[o], m_ch[o], s_ch[o]);
        }

        // ---- classification output (bit-exact: ascending) ----
#pragma unroll
        for (int o = 0; o < NC; ++o) {
            float acc = 0.f;
#pragma unroll
            for (int i = 0; i < CH; ++i) acc = fmaf(s_ch[i], cw.Wco[o * CH + i], acc);
            float s_unused;
            lif_update(acc + cw.bco[o], m_co[o], s_unused);
        }

        // ---- regression hidden: butterfly-tree association over 32-padded
        //      block (stride 16,8,4,2,1), bias after. Matches warp/Triton-style
        //      parallel reduce that XLA emits for this reduce-bearing branch. ----
        float s_rh[RH];
#pragma unroll
        for (int o = 0; o < RH; ++o) {
            float p[32];
#pragma unroll
            for (int i = 0; i < SH; ++i) p[i] = s_sh[i] * cw.Wrh[o * SH + i];
#pragma unroll
            for (int i = SH; i < 32; ++i) p[i] = 0.f;
#pragma unroll
            for (int s = 16; s >= 1; s >>= 1) {
#pragma unroll
                for (int i = 0; i < s; ++i) p[i] = p[i] + p[i + s];
            }
            lif_update(p[0] + cw.brh[o], m_rh[o], s_rh[o]);
        }

        // ---- regression output (keep sequential: currently passes) ----
        {
            float acc = 0.f;
#pragma unroll
            for (int i = 0; i < RH; ++i) acc = fmaf(s_rh[i], cw.Wro[i], acc);
            float s_unused;
            lif_update(acc + cw.bro[0], m_ro, s_unused);
        }

        // ---- stores ----
        p_mco[r * 3 + 0] = m_co[0];
        p_mco[r * 3 + 1] = m_co[1];
        p_mco[r * 3 + 2] = m_co[2];
        {
            float4* q = (float4*)(p_sch + r * 16);
            q[0] = make_float4(s_ch[0],  s_ch[1],  s_ch[2],  s_ch[3]);
            q[1] = make_float4(s_ch[4],  s_ch[5],  s_ch[6],  s_ch[7]);
            q[2] = make_float4(s_ch[8],  s_ch[9],  s_ch[10], s_ch[11]);
            q[3] = make_float4(s_ch[12], s_ch[13], s_ch[14], s_ch[15]);
        }
        p_mro[r] = m_ro;
        {
            float4* q = (float4*)(p_srh + r * 16);
            q[0] = make_float4(s_rh[0],  s_rh[1],  s_rh[2],  s_rh[3]);
            q[1] = make_float4(s_rh[4],  s_rh[5],  s_rh[6],  s_rh[7]);
            q[2] = make_float4(s_rh[8],  s_rh[9],  s_rh[10], s_rh[11]);
            q[3] = make_float4(s_rh[12], s_rh[13], s_rh[14], s_rh[15]);
        }
        {
            float4* q = (float4*)(p_ssh + r * 24);
            q[0] = make_float4(s_sh[0],  s_sh[1],  s_sh[2],  s_sh[3]);
            q[1] = make_float4(s_sh[4],  s_sh[5],  s_sh[6],  s_sh[7]);
            q[2] = make_float4(s_sh[8],  s_sh[9],  s_sh[10], s_sh[11]);
            q[3] = make_float4(s_sh[12], s_sh[13], s_sh[14], s_sh[15]);
            q[4] = make_float4(s_sh[16], s_sh[17], s_sh[18], s_sh[19]);
            q[5] = make_float4(s_sh[20], s_sh[21], s_sh[22], s_sh[23]);
        }
        {
            float4* q = (float4*)(p_sec + r * 8);
            q[0] = make_float4(s_ec[0], s_ec[1], s_ec[2], s_ec[3]);
            q[1] = make_float4(s_ec[4], s_ec[5], s_ec[6], s_ec[7]);
        }
        {
            float4* q = (float4*)(p_ser + r * 8);
            q[0] = make_float4(s_er[0], s_er[1], s_er[2], s_er[3]);
            q[1] = make_float4(s_er[4], s_er[5], s_er[6], s_er[7]);
        }
    }
}

extern "C" void kernel_launch(void* const* d_in, const int* in_sizes, int n_in,
                              void* d_out, int out_size)
{
    const float* x = (const float*)d_in[0];

#define CPY(field, idx, count) \
    cudaMemcpyToSymbolAsync(cw, d_in[idx], sizeof(float) * (count), \
                            offsetof(Weights, field), cudaMemcpyDeviceToDevice, 0)
    CPY(We_c, 1, EH * IN);
    CPY(be_c, 2, EH);
    CPY(We_r, 3, EH * IN);
    CPY(be_r, 4, EH);
    CPY(Ws,   5, SH * 2 * EH);
    CPY(bs,   6, SH);
    CPY(Wch,  7, CH * SH);
    CPY(bch,  8, CH);
    CPY(Wco,  9, NC * CH);
    CPY(bco, 10, NC);
    CPY(Wrh, 11, RH * SH);
    CPY(brh, 12, RH);
    CPY(Wro, 13, RH);
    CPY(bro, 14, 1);
#undef CPY

    snn_kernel<<<BB / 128, 128>>>(x, (float*)d_out);
}